// round 15
// baseline (speedup 1.0000x reference)
#include <cuda_runtime.h>
#include <cstdint>

#define L       8192
#define CHN     16
#define BATCH   32
#define NSTEPS  100
#define HSTEP   0.01f
#define TILEX   256
#define NTHR    64

typedef unsigned long long ull;

__device__ float g_z [(size_t)BATCH * CHN * L];
__device__ float g_k1[(size_t)BATCH * CHN * L];
__device__ float g_k2[(size_t)BATCH * CHN * L];
__device__ __align__(16) float g_wd[CHN * CHN * 12];

__device__ __forceinline__ ull pk2(float lo, float hi) {
    ull r; asm("mov.b64 %0, {%1,%2};" : "=l"(r) : "f"(lo), "f"(hi)); return r;
}
__device__ __forceinline__ void upk2(ull a, float& lo, float& hi) {
    asm("mov.b64 {%0,%1}, %2;" : "=f"(lo), "=f"(hi) : "l"(a));
}
__device__ __forceinline__ void fma2(ull &acc, ull a, ull b) {
    asm("fma.rn.f32x2 %0, %1, %2, %0;" : "+l"(acc) : "l"(a), "l"(b));
}

// one-time weight table: g_wd[ci][co][12] = [w0,w0,w1,w1][w2,w2,w3,w3][w4,w4,-,-]
__global__ void prep_w(const float* __restrict__ Wg) {
    for (int i = threadIdx.x; i < CHN * CHN * 5; i += 256) {
        int co = i / 80, r = i % 80, ci = r / 5, t = r % 5;
        float w = Wg[i];
        int base = (ci * 16 + co) * 12;
        g_wd[base + 2 * t]     = w;
        g_wd[base + 2 * t + 1] = w;
    }
}

// Store one 4-wide output chunk with ghost-cell handling.
// Interior formula valid for x in [10, 8181]; ghosts replicate those edges.
__device__ __forceinline__ void store_chunk(float* __restrict__ orow, int x,
                                            float f0, float f1, float f2, float f3) {
    if (x >= 12 && x <= 8176) {
        *(float4*)(orow + x) = make_float4(f0, f1, f2, f3);
    } else if (x == 8) {
        #pragma unroll
        for (int i = 0; i < 10; ++i) orow[i] = f2;
        orow[10] = f2; orow[11] = f3;
    } else if (x == 8180) {
        orow[8180] = f0; orow[8181] = f1;
        #pragma unroll
        for (int i = 0; i < 10; ++i) orow[8182 + i] = f1;
    }
}

// STAGE 1: out = B(z + h conv(z))
// STAGE 2: out = B(0.75 z + 0.25 k + 0.25 h conv(k))
// STAGE 3: out = B(z/3 + 2k/3 + (2h/3) conv(k))
template<int STAGE>
__global__ void __launch_bounds__(NTHR, 8)
stage_k(const float* __restrict__ zin, const float* __restrict__ kin,
        float* __restrict__ out)
{
    const int tid  = threadIdx.x;
    const int lane = tid & 31;
    const int w    = tid >> 5;             // 2 warps
    const int coo  = w * 8;                // cout base (0 or 8)
    const int b    = blockIdx.y;
    const int X0   = blockIdx.x * TILEX;

    const int xA = X0 + 4 * lane;          // segment A chunk
    const int xB = xA + 128;               // segment B chunk

    const int aA0 = (xA - 4 < 0) ? 0 : xA - 4;
    const int aB2 = (xB + 4 > L - 4) ? L - 4 : xB + 4;

    const float* csrc = (STAGE == 1 ? zin : kin) + (size_t)b * CHN * L;

    ull acc[8][4];   // acc[q][p]: lo = out[coo+q][xA+p], hi = out[coo+q][xB+p]
    #pragma unroll
    for (int q = 0; q < 8; ++q)
        #pragma unroll
        for (int j = 0; j < 4; ++j) acc[q][j] = 0ull;

    // per-warp ci phase stagger: warp 1 starts at ci=8; two constant-stride loops
    const int ci0 = w * 8;

    #pragma unroll 1
    for (int ph = 0; ph < 2; ++ph) {
        const int cbeg = ph == 0 ? ci0 : 0;
        const int cend = ph == 0 ? CHN : ci0;
        const float* rowp = csrc + (size_t)cbeg * L;
        const float* wrow = g_wd + (cbeg * 16 + coo) * 12;

        #pragma unroll 1
        for (int ci = cbeg; ci < cend; ++ci) {
            float4 cA0 = *(const float4*)(rowp + aA0);
            float4 cA1 = *(const float4*)(rowp + xA);
            float4 cA2 = *(const float4*)(rowp + xA + 4);
            float4 cB0 = *(const float4*)(rowp + xB - 4);
            float4 cB1 = *(const float4*)(rowp + xB);
            float4 cB2 = *(const float4*)(rowp + aB2);

            // strided pairs: P[j] = (vA[xA-2+j], vB[xB-2+j]); each value used once
            ull P0 = pk2(cA0.z, cB0.z), P1 = pk2(cA0.w, cB0.w);
            ull P2 = pk2(cA1.x, cB1.x), P3 = pk2(cA1.y, cB1.y);
            ull P4 = pk2(cA1.z, cB1.z), P5 = pk2(cA1.w, cB1.w);
            ull P6 = pk2(cA2.x, cB2.x), P7 = pk2(cA2.y, cB2.y);

            #pragma unroll
            for (int q = 0; q < 8; ++q) {
                ulonglong2 u01 = *(const ulonglong2*)(wrow + q * 12);
                ulonglong2 u23 = *(const ulonglong2*)(wrow + q * 12 + 4);
                ull W4 = *(const ull*)(wrow + q * 12 + 8);
                ull W0 = u01.x, W1 = u01.y, W2 = u23.x, W3 = u23.y;

                fma2(acc[q][0], P0, W0); fma2(acc[q][0], P1, W1);
                fma2(acc[q][0], P2, W2); fma2(acc[q][0], P3, W3);
                fma2(acc[q][0], P4, W4);
                fma2(acc[q][1], P1, W0); fma2(acc[q][1], P2, W1);
                fma2(acc[q][1], P3, W2); fma2(acc[q][1], P4, W3);
                fma2(acc[q][1], P5, W4);
                fma2(acc[q][2], P2, W0); fma2(acc[q][2], P3, W1);
                fma2(acc[q][2], P4, W2); fma2(acc[q][2], P5, W3);
                fma2(acc[q][2], P6, W4);
                fma2(acc[q][3], P3, W0); fma2(acc[q][3], P4, W1);
                fma2(acc[q][3], P5, W2); fma2(acc[q][3], P6, W3);
                fma2(acc[q][3], P7, W4);
            }
            rowp += L;
            wrow += 16 * 12;
        }
    }

    // ---- epilogue ----
    const float ca = (STAGE == 1) ? 1.0f  : (STAGE == 2) ? 0.75f         : (1.0f / 3.0f);
    const float cb = (STAGE == 1) ? 0.0f  : (STAGE == 2) ? 0.25f         : (2.0f / 3.0f);
    const float cc = (STAGE == 1) ? HSTEP : (STAGE == 2) ? 0.25f * HSTEP : (2.0f * HSTEP / 3.0f);

    const float* zb = zin + (size_t)b * CHN * L;
    const float* kb = (STAGE == 1) ? nullptr : kin + (size_t)b * CHN * L;
    float*       ob = out + (size_t)b * CHN * L;

    #pragma unroll
    for (int q = 0; q < 8; ++q) {
        const int co = coo + q;
        const float* zrow = zb + (size_t)co * L;
        float*       orow = ob + (size_t)co * L;

        float cvA[4], cvB[4];
        #pragma unroll
        for (int p = 0; p < 4; ++p) upk2(acc[q][p], cvA[p], cvB[p]);

        #pragma unroll
        for (int s = 0; s < 2; ++s) {
            const int x = (s == 0) ? xA : xB;
            const float* cv = (s == 0) ? cvA : cvB;

            float4 zv = *(const float4*)(zrow + x);
            float r0, r1, r2, r3;
            if (STAGE == 1) {
                r0 = fmaf(cc, cv[0], zv.x); r1 = fmaf(cc, cv[1], zv.y);
                r2 = fmaf(cc, cv[2], zv.z); r3 = fmaf(cc, cv[3], zv.w);
            } else {
                float4 kv = *(const float4*)(kb + (size_t)co * L + x);
                r0 = fmaf(ca, zv.x, fmaf(cb, kv.x, cc * cv[0]));
                r1 = fmaf(ca, zv.y, fmaf(cb, kv.y, cc * cv[1]));
                r2 = fmaf(ca, zv.z, fmaf(cb, kv.z, cc * cv[2]));
                r3 = fmaf(ca, zv.w, fmaf(cb, kv.w, cc * cv[3]));
            }
            store_chunk(orow, x, r0, r1, r2, r3);
        }
    }
}

extern "C" void kernel_launch(void* const* d_in, const int* in_sizes, int n_in,
                              void* d_out, int out_size) {
    const float* z0 = (const float*)d_in[0];
    const float* W  = (const float*)d_in[1];
    float* out = (float*)d_out;

    float *zscr, *k1, *k2;
    cudaGetSymbolAddress((void**)&zscr, g_z);
    cudaGetSymbolAddress((void**)&k1,   g_k1);
    cudaGetSymbolAddress((void**)&k2,   g_k2);

    prep_w<<<1, 256>>>(W);

    dim3 grid(L / TILEX, BATCH);   // (32, 32) = 1024 CTAs of 64 threads
    for (int s = 0; s < NSTEPS; ++s) {
        const float* src;
        float* dst;
        if (s == 0)      { src = z0;   dst = zscr; }
        else if (s & 1)  { src = zscr; dst = out;  }
        else             { src = out;  dst = zscr; }

        stage_k<1><<<grid, NTHR>>>(src, src, k1);
        stage_k<2><<<grid, NTHR>>>(src, k1,  k2);
        stage_k<3><<<grid, NTHR>>>(src, k2,  dst);
    }
}

// round 16
// speedup vs baseline: 1.5603x; 1.5603x over previous
#include <cuda_runtime.h>
#include <cstdint>

#define L       8192
#define CHN     16
#define BATCH   32
#define NSTEPS  100
#define HSTEP   0.01f
#define TILEX   128
#define NTHR    64

typedef unsigned int u32;

__device__ float g_z [(size_t)BATCH * CHN * L];
__device__ float g_k1[(size_t)BATCH * CHN * L];
__device__ float g_k2[(size_t)BATCH * CHN * L];
// B matrices, [k=80][co=16], tf32-rounded hi and residual lo
__device__ __align__(16) float g_bhi[80 * 16];
__device__ __align__(16) float g_blo[80 * 16];

__device__ __forceinline__ u32 f2tf32(float v) {
    u32 r; asm("cvt.rna.tf32.f32 %0, %1;" : "=r"(r) : "f"(v)); return r;
}

__device__ __forceinline__ void mma_tf32(float* d,
                                         u32 a0, u32 a1, u32 a2, u32 a3,
                                         u32 b0, u32 b1) {
    asm volatile(
        "mma.sync.aligned.m16n8k8.row.col.f32.tf32.tf32.f32 "
        "{%0,%1,%2,%3}, {%4,%5,%6,%7}, {%8,%9}, {%0,%1,%2,%3};"
        : "+f"(d[0]), "+f"(d[1]), "+f"(d[2]), "+f"(d[3])
        : "r"(a0), "r"(a1), "r"(a2), "r"(a3), "r"(b0), "r"(b1));
}

// one-time: B[k][co] = W[co][ci][tap] with k = tap*16+ci, split hi/lo
__global__ void prep_b(const float* __restrict__ W) {
    for (int i = threadIdx.x; i < 80 * 16; i += 256) {
        int k = i >> 4, co = i & 15;
        int tap = k >> 4, ci = k & 15;
        float w = W[(co * 16 + ci) * 5 + tap];
        float hi = __uint_as_float(f2tf32(w));
        g_bhi[i] = hi;
        g_blo[i] = __uint_as_float(f2tf32(w - hi));
    }
}

// STAGE 1: out = B(z + h conv(z))
// STAGE 2: out = B(0.75 z + 0.25 k + 0.25 h conv(k))
// STAGE 3: out = B(z/3 + 2k/3 + (2h/3) conv(k))
template<int STAGE>
__global__ void __launch_bounds__(NTHR, 8)
stage_k(const float* __restrict__ zin, const float* __restrict__ kin,
        float* __restrict__ out)
{
    const int lane = threadIdx.x & 31;
    const int gid  = lane >> 2;            // 0..7
    const int tid4 = lane & 3;             // 0..3
    const int w    = threadIdx.x >> 5;     // 0..1
    const int b    = blockIdx.y;
    const int xw   = blockIdx.x * TILEX + w * 64;

    const float* src = (STAGE == 1 ? zin : kin) + (size_t)b * CHN * L;

    // D accumulators: d[nt][mt][r]; (x, co) per PTX m16n8k8 C-fragment layout
    float d[2][4][4];
    #pragma unroll
    for (int nt = 0; nt < 2; ++nt)
        #pragma unroll
        for (int mt = 0; mt < 4; ++mt)
            #pragma unroll
            for (int r = 0; r < 4; ++r) d[nt][mt][r] = 0.0f;

    #pragma unroll 1
    for (int c = 0; c < 10; ++c) {
        const int tap = c >> 1;
        const int cil = ((c & 1) << 3) + tid4;     // ci for k = c*8+tid4

        // B fragments: b0 at k=c*8+tid4, b1 at k+4; col = nt*8+gid
        const float* bhp = g_bhi + (c * 8 + tid4) * 16 + gid;
        const float* blp = g_blo + (c * 8 + tid4) * 16 + gid;
        u32 bh0[2], bh1[2], bl0[2], bl1[2];
        #pragma unroll
        for (int nt = 0; nt < 2; ++nt) {
            bh0[nt] = __float_as_uint(bhp[nt * 8]);
            bh1[nt] = __float_as_uint(bhp[64 + nt * 8]);   // +4 k-rows = +4*16
            bl0[nt] = __float_as_uint(blp[nt * 8]);
            bl1[nt] = __float_as_uint(blp[64 + nt * 8]);
        }

        const float* plo = src + (size_t)cil * L;       // ci for a0/a1
        const float* phi = plo + 4 * L;                  // ci+4 for a2/a3
        const int xoff = xw + gid + tap - 2;

        #pragma unroll
        for (int mt = 0; mt < 4; ++mt) {
            int x0 = xoff + mt * 16;           // rows gid
            int x1 = x0 + 8;                   // rows gid+8
            x0 = x0 < 0 ? 0 : x0;              // clamp corrupts only ghost rows
            x1 = x1 > L - 1 ? L - 1 : x1;
            float v0 = plo[x0], v1 = plo[x1], v2 = phi[x0], v3 = phi[x1];

            u32 ah0 = f2tf32(v0), ah1 = f2tf32(v1), ah2 = f2tf32(v2), ah3 = f2tf32(v3);
            u32 al0 = f2tf32(v0 - __uint_as_float(ah0));
            u32 al1 = f2tf32(v1 - __uint_as_float(ah1));
            u32 al2 = f2tf32(v2 - __uint_as_float(ah2));
            u32 al3 = f2tf32(v3 - __uint_as_float(ah3));

            #pragma unroll
            for (int nt = 0; nt < 2; ++nt) {
                float* dd = d[nt][mt];
                mma_tf32(dd, ah0, ah1, ah2, ah3, bh0[nt], bh1[nt]);
                mma_tf32(dd, ah0, ah1, ah2, ah3, bl0[nt], bl1[nt]);
                mma_tf32(dd, al0, al1, al2, al3, bh0[nt], bh1[nt]);
            }
        }
    }

    // ---- epilogue: combine + store with ghost handling ----
    const float ca = (STAGE == 1) ? 1.0f  : (STAGE == 2) ? 0.75f         : (1.0f / 3.0f);
    const float cb = (STAGE == 1) ? 0.0f  : (STAGE == 2) ? 0.25f         : (2.0f / 3.0f);
    const float cc = (STAGE == 1) ? HSTEP : (STAGE == 2) ? 0.25f * HSTEP : (2.0f * HSTEP / 3.0f);

    const float* zb = zin + (size_t)b * CHN * L;
    const float* kb = (STAGE == 1) ? nullptr : kin + (size_t)b * CHN * L;
    float*       ob = out + (size_t)b * CHN * L;

    #pragma unroll
    for (int nt = 0; nt < 2; ++nt) {
        #pragma unroll
        for (int mt = 0; mt < 4; ++mt) {
            #pragma unroll
            for (int r = 0; r < 4; ++r) {
                const int x  = xw + mt * 16 + gid + ((r & 2) ? 8 : 0);
                const int co = nt * 8 + 2 * tid4 + (r & 1);
                const float conv = d[nt][mt][r];

                const float* zrow = zb + (size_t)co * L;
                float*       orow = ob + (size_t)co * L;

                float res;
                if (STAGE == 1) {
                    res = fmaf(cc, conv, zrow[x]);
                } else {
                    float kv = (kb + (size_t)co * L)[x];
                    res = fmaf(ca, zrow[x], fmaf(cb, kv, cc * conv));
                }

                if (x >= 10 && x <= 8181) orow[x] = res;
                if (x == 10) {
                    #pragma unroll
                    for (int i = 0; i < 10; ++i) orow[i] = res;
                }
                if (x == 8181) {
                    #pragma unroll
                    for (int i = 0; i < 10; ++i) orow[8182 + i] = res;
                }
            }
        }
    }
}

extern "C" void kernel_launch(void* const* d_in, const int* in_sizes, int n_in,
                              void* d_out, int out_size) {
    const float* z0 = (const float*)d_in[0];
    const float* W  = (const float*)d_in[1];
    float* out = (float*)d_out;

    float *zscr, *k1, *k2;
    cudaGetSymbolAddress((void**)&zscr, g_z);
    cudaGetSymbolAddress((void**)&k1,   g_k1);
    cudaGetSymbolAddress((void**)&k2,   g_k2);

    prep_b<<<1, 256>>>(W);

    dim3 grid(L / TILEX, BATCH);   // (64, 32) = 2048 CTAs of 64 threads
    for (int s = 0; s < NSTEPS; ++s) {
        const float* src;
        float* dst;
        if (s == 0)      { src = z0;   dst = zscr; }
        else if (s & 1)  { src = zscr; dst = out;  }
        else             { src = out;  dst = zscr; }

        stage_k<1><<<grid, NTHR>>>(src, src, k1);
        stage_k<2><<<grid, NTHR>>>(src, k1,  k2);
        stage_k<3><<<grid, NTHR>>>(src, k2,  dst);
    }
}